// round 16
// baseline (speedup 1.0000x reference)
#include <cuda_runtime.h>
#include <cuda_bf16.h>
#include <math.h>
#include <cstdint>

// Problem constants
#define BB 2
#define TT 1024
#define CC 2048
#define HH 32
#define NN 64
#define BT (BB*TT)              // 2048
#define BTC (BB*TT*CC)          // 4194304  (== CC*CC)

// ---------------------------------------------------------------------------
// Scratch (static device memory)
// ---------------------------------------------------------------------------
enum { S_XW=0, S_XA, S_XV, S_XG, S_R, S_K, S_V,
       S_DECAY, S_ASIG, S_G, S_AW, S_BW, S_KF, S_VF, S_O, S_DR, N_F32 };
enum { B_XRH=0, B_XRL, B_XKH, B_XKL, B_XVH, B_XVL, B_XOH, B_XOL,
       B_WRH, B_WRL, B_WKH, B_WKL, B_WVH, B_WVL, B_WOH, B_WOL, N_BF16 };
#define BF16_BASE ((size_t)N_F32*BTC)                 // in floats
#define U_OFF     (BF16_BASE + (size_t)N_BF16*BTC/2)  // bf16 U region
#define BR_OFF    (U_OFF + (size_t)BT*288)
#define KR_OFF    (BR_OFF + (size_t)BB*HH*TT)
#define V2T_OFF   (KR_OFF + (size_t)BB*HH*TT)         // bf16 V2T region
#define SCRATCH_FLOATS (V2T_OFF + (size_t)CC*288 + 256)

__device__ float g_scratch[SCRATCH_FLOATS];

// ---------------------------------------------------------------------------
// PTX helpers
// ---------------------------------------------------------------------------
__device__ __forceinline__ uint32_t smem_u32(const void* p) {
    uint32_t a;
    asm("{ .reg .u64 t; cvta.to.shared.u64 t, %1; cvt.u32.u64 %0, t; }" : "=r"(a) : "l"(p));
    return a;
}
#define CP16(dst, src) \
    asm volatile("cp.async.cg.shared.global [%0], [%1], 16;" :: "r"(dst), "l"(src))
#define CP_COMMIT() asm volatile("cp.async.commit_group;" ::: "memory")
#define LDSM4(r, addr) \
    asm volatile("ldmatrix.sync.aligned.m8n8.x4.shared.b16 {%0,%1,%2,%3}, [%4];" \
        : "=r"((r)[0]), "=r"((r)[1]), "=r"((r)[2]), "=r"((r)[3]) : "r"(addr))
#define MMA16816(d, a, b0, b1) \
    asm volatile("mma.sync.aligned.m16n8k16.row.col.f32.bf16.bf16.f32 " \
        "{%0,%1,%2,%3}, {%4,%5,%6,%7}, {%8,%9}, {%0,%1,%2,%3};" \
        : "+f"((d)[0]), "+f"((d)[1]), "+f"((d)[2]), "+f"((d)[3]) \
        : "r"((a)[0]), "r"((a)[1]), "r"((a)[2]), "r"((a)[3]), "r"(b0), "r"(b1))

__device__ __forceinline__ void split_hilo(float v, __nv_bfloat16& h, __nv_bfloat16& l) {
    h = __float2bfloat16(v);
    l = __float2bfloat16(v - __bfloat162float(h));
}
__device__ __forceinline__ void store_hilo4(__nv_bfloat16* hi, __nv_bfloat16* lo,
                                            size_t off, float4 v) {
    __nv_bfloat16 hv[4], lv[4];
    split_hilo(v.x, hv[0], lv[0]); split_hilo(v.y, hv[1], lv[1]);
    split_hilo(v.z, hv[2], lv[2]); split_hilo(v.w, hv[3], lv[3]);
    *(uint2*)&hi[off] = *(uint2*)hv;
    *(uint2*)&lo[off] = *(uint2*)lv;
}

// ---------------------------------------------------------------------------
// K0a: batched fp32 -> bf16 hi/lo conversion (4 big weights)
// ---------------------------------------------------------------------------
struct CvtJobs { const float* x[4]; __nv_bfloat16* hi[4]; __nv_bfloat16* lo[4]; };

__global__ __launch_bounds__(256) void cvt_all_kernel(CvtJobs jobs)
{
    const int z = blockIdx.y;
    size_t i = ((size_t)blockIdx.x * 256 + threadIdx.x) * 4;
    float4 v = *(const float4*)&jobs.x[z][i];
    store_hilo4(jobs.hi[z], jobs.lo[z], i, v);
}

// ---------------------------------------------------------------------------
// K0b: V2 transpose + hi/lo: src [D, CC] fp32 -> dst [CC, D] bf16 hi/lo
// ---------------------------------------------------------------------------
struct V2tJobs { const float* src[4]; __nv_bfloat16* dh[4]; __nv_bfloat16* dl[4]; int D[4]; };

__global__ __launch_bounds__(256) void cvt_v2t_kernel(V2tJobs jobs)
{
    const int z = blockIdx.y;
    const int D = jobs.D[z];
    int i = blockIdx.x * 256 + threadIdx.x;
    if (i >= CC * D) return;
    int c = i / D, d = i - c * D;
    float v = jobs.src[z][(size_t)d * CC + c];
    __nv_bfloat16 h, l;
    split_hilo(v, h, l);
    jobs.dh[z][i] = h;
    jobs.dl[z][i] = l;
}

// ---------------------------------------------------------------------------
// K1: token shift + 6-way mix
// ---------------------------------------------------------------------------
__global__ __launch_bounds__(256) void mix_kernel(
    const float* __restrict__ h, const float* __restrict__ shift,
    const float* __restrict__ mr, const float* __restrict__ mw,
    const float* __restrict__ mk, const float* __restrict__ mv,
    const float* __restrict__ ma, const float* __restrict__ mg,
    __nv_bfloat16* __restrict__ xrh, __nv_bfloat16* __restrict__ xrl,
    float* __restrict__ oxw,
    __nv_bfloat16* __restrict__ xkh, __nv_bfloat16* __restrict__ xkl,
    float* __restrict__ oxv,
    __nv_bfloat16* __restrict__ xvh, __nv_bfloat16* __restrict__ xvl,
    float* __restrict__ oxa, float* __restrict__ oxg)
{
    int gid = blockIdx.x * 256 + threadIdx.x;
    int row = gid >> 9;
    int c   = (gid & 511) << 2;
    int t   = row & (TT-1);
    int b   = row >> 10;
    size_t off = (size_t)row * CC + c;

    float4 hv = *(const float4*)&h[off];
    float4 pv;
    if (t == 0) pv = *(const float4*)&shift[(size_t)b*CC + c];
    else        pv = *(const float4*)&h[off - CC];
    float4 xx = make_float4(pv.x-hv.x, pv.y-hv.y, pv.z-hv.z, pv.w-hv.w);

#define MIXV(mvec, o)                                                 \
    {   float4 m = *(const float4*)&mvec[c];                          \
        o = make_float4(hv.x + xx.x*m.x, hv.y + xx.y*m.y,             \
                        hv.z + xx.z*m.z, hv.w + xx.w*m.w); }
    float4 vr; MIXV(mr, vr); store_hilo4(xrh, xrl, off, vr);
    float4 vw; MIXV(mw, vw); *(float4*)&oxw[off] = vw;
    float4 vk; MIXV(mk, vk); store_hilo4(xkh, xkl, off, vk);
    float4 vv; MIXV(mv, vv); *(float4*)&oxv[off] = vv; store_hilo4(xvh, xvl, off, vv);
    float4 va; MIXV(ma, va); *(float4*)&oxa[off] = va;
    float4 vg; MIXV(mg, vg); *(float4*)&oxg[off] = vg;
#undef MIXV
}

// ---------------------------------------------------------------------------
// K2: FUSED HMMA bf16x3 GEMM + LoRA stage 1.
//     CTA tile 128x128, warp tile 64x32, 3-stage x 32KB ring -> 2 CTAs/SM.
// ---------------------------------------------------------------------------
#define GSTAGES 3
#define TILE_A 8192              // 128 rows x 64 B
#define TILE_B 8192              // 128 rows x 64 B
#define STAGE_B (2*TILE_A + 2*TILE_B)    // 32768
#define GEMM_SMEM (GSTAGES*STAGE_B)      // 98304

struct GemmJob  { const __nv_bfloat16 *Ah, *Al, *Bh, *Bl; float* Y; };
struct Lora1Job { const float* X; const float* G;
                  __nv_bfloat16* Uh; __nv_bfloat16* Ul; int D; int col0; int act; };
struct FusedJobs { GemmJob g[3]; Lora1Job l[5]; };

__device__ __forceinline__ uint32_t swz(uint32_t row, uint32_t chunk) {
    return row*64u + ((chunk ^ ((row >> 1) & 3u)) << 4);
}

__device__ void gemm_path(const GemmJob& gj, char* dynsmem)
{
    const __nv_bfloat16* __restrict__ Ahi = gj.Ah;
    const __nv_bfloat16* __restrict__ Alo = gj.Al;
    const __nv_bfloat16* __restrict__ Bhi = gj.Bh;
    const __nv_bfloat16* __restrict__ Blo = gj.Bl;
    float* __restrict__ Y = gj.Y;

    const uint32_t sb = smem_u32(dynsmem);
    const int tid  = threadIdx.x;
    const int lane = tid & 31;
    const int warp = tid >> 5;
    const int wm = warp >> 2;            // 0..1 (64 rows each)
    const int wn = warp & 3;             // 0..3 (32 cols each)
    const int bm = blockIdx.y << 7;
    const int bn = blockIdx.x << 7;

    auto load_stage = [&](int chunk, int stage) {
        const uint32_t st = sb + (uint32_t)stage * STAGE_B;
        const int k0 = chunk << 5;
#pragma unroll
        for (int i = 0; i < 2; i++) {                  // A: 512 float4
            int idx = tid + (i << 8);
            int row = idx >> 2, ch = idx & 3;
            uint32_t d = st + swz(row, ch);
            size_t g = (size_t)(bm + row) * CC + k0 + ch * 8;
            CP16(d,          Ahi + g);
            CP16(d + TILE_A, Alo + g);
        }
#pragma unroll
        for (int i = 0; i < 2; i++) {                  // B: 512 float4
            int idx = tid + (i << 8);
            int row = idx >> 2, ch = idx & 3;
            uint32_t d = st + 2*TILE_A + swz(row, ch);
            size_t g = (size_t)(bn + row) * CC + k0 + ch * 8;
            CP16(d,          Bhi + g);
            CP16(d + TILE_B, Blo + g);
        }
    };

    float acc[4][4][4];
#pragma unroll
    for (int mi=0;mi<4;mi++)
#pragma unroll
        for (int ni=0;ni<4;ni++)
#pragma unroll
            for (int j=0;j<4;j++) acc[mi][ni][j] = 0.f;

#pragma unroll
    for (int s = 0; s < 2; s++) { load_stage(s, s); CP_COMMIT(); }

    const int a_row = wm*64 + (lane & 7) + ((lane >> 3) & 1) * 8;
    const int a_ch  = (lane >> 4);
    const int b_row = wn*32 + (lane & 7) + (lane >> 4) * 8;
    const int b_ch  = ((lane >> 3) & 1);

    for (int it = 0; it < 64; it++) {
        const uint32_t st = sb + (uint32_t)(it % 3) * STAGE_B;
        asm volatile("cp.async.wait_group 1;" ::: "memory");
        __syncthreads();
        if (it + 2 < 64) load_stage(it + 2, (it + 2) % 3);
        CP_COMMIT();

#pragma unroll
        for (int ks = 0; ks < 2; ks++) {
            uint32_t ah[4][4], al[4][4], bh[2][4], bl[2][4];
#pragma unroll
            for (int mi = 0; mi < 4; mi++) {
                uint32_t a = st + swz((uint32_t)(a_row + mi*16), (uint32_t)(a_ch + ks*2));
                LDSM4(ah[mi], a);
            }
#pragma unroll
            for (int j = 0; j < 2; j++) {
                uint32_t baddr = st + 2*TILE_A +
                    swz((uint32_t)(b_row + j*16), (uint32_t)(b_ch + ks*2));
                LDSM4(bh[j], baddr);
            }
            // pass 1: ah * bh
#pragma unroll
            for (int mi = 0; mi < 4; mi++)
#pragma unroll
                for (int ni = 0; ni < 4; ni++)
                    MMA16816(acc[mi][ni], ah[mi], bh[ni>>1][(ni&1)*2], bh[ni>>1][(ni&1)*2+1]);
            // pass 2: ah * bl
#pragma unroll
            for (int j = 0; j < 2; j++) {
                uint32_t baddr = st + 2*TILE_A + TILE_B +
                    swz((uint32_t)(b_row + j*16), (uint32_t)(b_ch + ks*2));
                LDSM4(bl[j], baddr);
            }
#pragma unroll
            for (int mi = 0; mi < 4; mi++)
#pragma unroll
                for (int ni = 0; ni < 4; ni++)
                    MMA16816(acc[mi][ni], ah[mi], bl[ni>>1][(ni&1)*2], bl[ni>>1][(ni&1)*2+1]);
            // pass 3: al * bh
#pragma unroll
            for (int mi = 0; mi < 4; mi++) {
                uint32_t a = st + swz((uint32_t)(a_row + mi*16), (uint32_t)(a_ch + ks*2));
                LDSM4(al[mi], a + TILE_A);
            }
#pragma unroll
            for (int mi = 0; mi < 4; mi++)
#pragma unroll
                for (int ni = 0; ni < 4; ni++)
                    MMA16816(acc[mi][ni], al[mi], bh[ni>>1][(ni&1)*2], bh[ni>>1][(ni&1)*2+1]);
        }
    }

    const int erow = bm + wm*64 + (lane >> 2);
    const int ecol = bn + wn*32 + (lane & 3) * 2;
#pragma unroll
    for (int mi = 0; mi < 4; mi++)
#pragma unroll
        for (int ni = 0; ni < 4; ni++) {
            size_t r0 = (size_t)(erow + mi*16) * CC + ecol + ni*8;
            *(float2*)&Y[r0]        = make_float2(acc[mi][ni][0], acc[mi][ni][1]);
            *(float2*)&Y[r0 + 8*CC] = make_float2(acc[mi][ni][2], acc[mi][ni][3]);
        }
}

__device__ void lora_path(const Lora1Job& jb, int mblk, char* dynsmem)
{
    const float* __restrict__ X = jb.X;
    const float* __restrict__ G = jb.G;
    const int D = jb.D, col0 = jb.col0, act = jb.act;

    float* Xs = (float*)dynsmem;            // [32][68]
    float* Gs = Xs + 32*68;                 // [32][64]

    const int tid = threadIdx.x;
    const int bm = mblk * 64;
    const int tx = tid & 15;
    const int ty = tid >> 4;

    float4 px[2], pg[2];
    const int xrow = tid & 63;
    const int xkc0 = (tid >> 6) << 2;
    const int gkr0 = tid >> 4;
    const int gcc  = (tid & 15) << 2;

    auto gload = [&](int k0) {
#pragma unroll
        for (int i = 0; i < 2; i++) {
            px[i] = *(const float4*)&X[(size_t)(bm + xrow)*CC + k0 + xkc0 + i*16];
            if (col0 + gcc < D)
                pg[i] = *(const float4*)&G[(size_t)(k0 + gkr0 + i*16)*D + col0 + gcc];
            else
                pg[i] = make_float4(0.f, 0.f, 0.f, 0.f);
        }
    };
    auto sstore = [&]() {
#pragma unroll
        for (int i = 0; i < 2; i++) {
            int kc = xkc0 + i*16;
            Xs[(kc+0)*68+xrow] = px[i].x; Xs[(kc+1)*68+xrow] = px[i].y;
            Xs[(kc+2)*68+xrow] = px[i].z; Xs[(kc+3)*68+xrow] = px[i].w;
            *(float4*)&Gs[(gkr0 + i*16)*64 + gcc] = pg[i];
        }
    };

    float acc[4][4];
#pragma unroll
    for (int i=0;i<4;i++)
#pragma unroll
        for (int j=0;j<4;j++) acc[i][j] = 0.f;

    gload(0); sstore(); __syncthreads();

    for (int k0 = 32; k0 <= 2048; k0 += 32) {
        if (k0 < 2048) gload(k0);
#pragma unroll
        for (int kk = 0; kk < 32; kk++) {
            float4 xa = *(const float4*)&Xs[kk*68 + ty*4];
            float4 gb = *(const float4*)&Gs[kk*64 + tx*4];
            float xv[4] = {xa.x, xa.y, xa.z, xa.w};
            float gv[4] = {gb.x, gb.y, gb.z, gb.w};
#pragma unroll
            for (int i=0;i<4;i++)
#pragma unroll
                for (int j=0;j<4;j++)
                    acc[i][j] += xv[i]*gv[j];
        }
        __syncthreads();
        if (k0 < 2048) { sstore(); __syncthreads(); }
    }

#pragma unroll
    for (int i=0;i<4;i++) {
        int row = bm + ty*4 + i;
#pragma unroll
        for (int j=0;j<4;j++) {
            int col = col0 + tx*4 + j;
            if (col < D) {
                float y = acc[i][j];
                if (act == 1) y = tanhf(y);
                else if (act == 2) y = 1.f/(1.f+expf(-y));
                __nv_bfloat16 hv, lv;
                split_hilo(y, hv, lv);
                jb.Uh[(size_t)row*D + col] = hv;
                jb.Ul[(size_t)row*D + col] = lv;
            }
        }
    }
}

__global__ __launch_bounds__(256, 2) void gemm_lora_kernel(FusedJobs jobs, int nz_gemm)
{
    extern __shared__ char dynsmem[];
    const int z = blockIdx.z;
    if (z < nz_gemm) {
        gemm_path(jobs.g[z], dynsmem);
    } else {
        int lin = (z - nz_gemm)*256 + blockIdx.y*16 + blockIdx.x;
        if (lin >= 160) return;
        lora_path(jobs.l[lin >> 5], lin & 31, dynsmem);
    }
}

// ---------------------------------------------------------------------------
// K4: stage2 on HMMA (128x128 tile, 2 CTAs/SM)
// ---------------------------------------------------------------------------
struct S2Job  { const __nv_bfloat16 *Ah, *Al, *Bh, *Bl; const float* bias;
                float* out; const float* e1; const float* e2; int D; int mode; };
struct S2Jobs { S2Job j[4]; };

__global__ __launch_bounds__(256, 2) void stage2_hmma(S2Jobs jobs)
{
    extern __shared__ char dynsmem[];
    const S2Job jb = jobs.j[blockIdx.z];
    const int D = jb.D, nk = D >> 5, mode = jb.mode;

    const uint32_t sb = smem_u32(dynsmem);
    const int tid  = threadIdx.x;
    const int lane = tid & 31;
    const int warp = tid >> 5;
    const int wm = warp >> 2;
    const int wn = warp & 3;
    const int bm = blockIdx.y << 7;
    const int bn = blockIdx.x << 7;

    auto load_stage = [&](int chunk, int stage) {
        const uint32_t st = sb + (uint32_t)stage * STAGE_B;
        const int k0 = chunk << 5;
#pragma unroll
        for (int i = 0; i < 2; i++) {
            int idx = tid + (i << 8);
            int row = idx >> 2, ch = idx & 3;
            uint32_t d = st + swz(row, ch);
            size_t g = (size_t)(bm + row) * D + k0 + ch * 8;
            CP16(d,          jb.Ah + g);
            CP16(d + TILE_A, jb.Al + g);
        }
#pragma unroll
        for (int i = 0; i < 2; i++) {
            int idx = tid + (i << 8);
            int row = idx >> 2, ch = idx & 3;
            uint32_t d = st + 2*TILE_A + swz(row, ch);
            size_t g = (size_t)(bn + row) * D + k0 + ch * 8;
            CP16(d,          jb.Bh + g);
            CP16(d + TILE_B, jb.Bl + g);
        }
    };

    float acc[4][4][4];
#pragma unroll
    for (int mi=0;mi<4;mi++)
#pragma unroll
        for (int ni=0;ni<4;ni++)
#pragma unroll
            for (int j=0;j<4;j++) acc[mi][ni][j] = 0.f;

#pragma unroll
    for (int s = 0; s < 2; s++) {
        if (s < nk) load_stage(s, s);
        CP_COMMIT();
    }

    const int a_row = wm*64 + (lane & 7) + ((lane >> 3) & 1) * 8;
    const int a_ch  = (lane >> 4);
    const int b_row = wn*32 + (lane & 7) + (lane >> 4) * 8;
    const int b_ch  = ((lane >> 3) & 1);

    for (int it = 0; it < nk; it++) {
        const uint32_t st = sb + (uint32_t)(it % 3) * STAGE_B;
        asm volatile("cp.async.wait_group 1;" ::: "memory");
        __syncthreads();
        if (it + 2 < nk) load_stage(it + 2, (it + 2) % 3);
        CP_COMMIT();

#pragma unroll
        for (int ks = 0; ks < 2; ks++) {
            uint32_t ah[4][4], al[4][4], bh[2][4], bl[2][4];
#pragma unroll
            for (int mi = 0; mi < 4; mi++) {
                uint32_t a = st + swz((uint32_t)(a_row + mi*16), (uint32_t)(a_ch + ks*2));
                LDSM4(ah[mi], a);
            }
#pragma unroll
            for (int j = 0; j < 2; j++) {
                uint32_t baddr = st + 2*TILE_A +
                    swz((uint32_t)(b_row + j*16), (uint32_t)(b_ch + ks*2));
                LDSM4(bh[j], baddr);
            }
#pragma unroll
            for (int mi = 0; mi < 4; mi++)
#pragma unroll
                for (int ni = 0; ni < 4; ni++)
                    MMA16816(acc[mi][ni], ah[mi], bh[ni>>1][(ni&1)*2], bh[ni>>1][(ni&1)*2+1]);
#pragma unroll
            for (int j = 0; j < 2; j++) {
                uint32_t baddr = st + 2*TILE_A + TILE_B +
                    swz((uint32_t)(b_row + j*16), (uint32_t)(b_ch + ks*2));
                LDSM4(bl[j], baddr);
            }
#pragma unroll
            for (int mi = 0; mi < 4; mi++)
#pragma unroll
                for (int ni = 0; ni < 4; ni++)
                    MMA16816(acc[mi][ni], ah[mi], bl[ni>>1][(ni&1)*2], bl[ni>>1][(ni&1)*2+1]);
#pragma unroll
            for (int mi = 0; mi < 4; mi++) {
                uint32_t a = st + swz((uint32_t)(a_row + mi*16), (uint32_t)(a_ch + ks*2));
                LDSM4(al[mi], a + TILE_A);
            }
#pragma unroll
            for (int mi = 0; mi < 4; mi++)
#pragma unroll
                for (int ni = 0; ni < 4; ni++)
                    MMA16816(acc[mi][ni], al[mi], bh[ni>>1][(ni&1)*2], bh[ni>>1][(ni&1)*2+1]);
        }
    }

    const int erow = bm + wm*64 + (lane >> 2);
    const int ecol = bn + wn*32 + (lane & 3) * 2;
#pragma unroll
    for (int mi = 0; mi < 4; mi++)
#pragma unroll
        for (int ni = 0; ni < 4; ni++) {
            const int c = ecol + ni*8;
            size_t r0 = (size_t)(erow + mi*16) * CC + c;
            float2 p0 = make_float2(acc[mi][ni][0], acc[mi][ni][1]);
            float2 p1 = make_float2(acc[mi][ni][2], acc[mi][ni][3]);
            if (mode == 3) {
                *(float2*)&jb.out[r0]        = p0;
                *(float2*)&jb.out[r0 + 8*CC] = p1;
            } else {
                float b0 = jb.bias[c], b1 = jb.bias[c+1];
                float s00 = 1.f/(1.f+expf(-(p0.x+b0)));
                float s01 = 1.f/(1.f+expf(-(p0.y+b1)));
                float s10 = 1.f/(1.f+expf(-(p1.x+b0)));
                float s11 = 1.f/(1.f+expf(-(p1.y+b1)));
                if (mode == 0) {
                    const float e = 0.6065306597126334f;
                    *(float2*)&jb.out[r0]        = make_float2(e*s00, e*s01);
                    *(float2*)&jb.out[r0 + 8*CC] = make_float2(e*s10, e*s11);
                } else if (mode == 1) {
                    *(float2*)&jb.out[r0]        = make_float2(s00, s01);
                    *(float2*)&jb.out[r0 + 8*CC] = make_float2(s10, s11);
                } else {
                    float2 a0 = *(const float2*)&jb.e1[r0];
                    float2 f0 = *(const float2*)&jb.e2[r0];
                    float2 a1 = *(const float2*)&jb.e1[r0 + 8*CC];
                    float2 f1 = *(const float2*)&jb.e2[r0 + 8*CC];
                    *(float2*)&jb.out[r0] =
                        make_float2(a0.x + (f0.x-a0.x)*s00, a0.y + (f0.y-a0.y)*s01);
                    *(float2*)&jb.out[r0 + 8*CC] =
                        make_float2(a1.x + (f1.x-a1.x)*s10, a1.y + (f1.y-a1.y)*s11);
                }
            }
        }
}

// ---------------------------------------------------------------------------
// K5: per-(b,t,h) prep + per-step scalars + dr = decay*r
// ---------------------------------------------------------------------------
__global__ __launch_bounds__(256) void prep_kernel(
    const float* __restrict__ k, const float* __restrict__ r,
    const float* __restrict__ asig, const float* __restrict__ decay,
    const float* __restrict__ kkvec, const float* __restrict__ kavec,
    float* __restrict__ aw, float* __restrict__ bw, float* __restrict__ kf,
    float* __restrict__ drb,
    float* __restrict__ brg, float* __restrict__ krg)
{
    const int tid = threadIdx.x;
    const int g = tid >> 6, n = tid & 63;
    const size_t head = (size_t)blockIdx.x*4 + g;
    const size_t idx = head*64 + n;
    const int c = (int)(idx & (CC-1));

    float kv = k[idx];
    float kk = kv * kkvec[c];
    float ss = kk*kk;
#pragma unroll
    for (int off=16; off; off>>=1) ss += __shfl_xor_sync(0xffffffffu, ss, off);
    __shared__ float red[8];
    if ((tid & 31)==0) red[tid>>5] = ss;
    __syncthreads();
    float tot = red[g*2] + red[g*2+1];
    float inv = 1.f / fmaxf(sqrtf(tot), 1e-12f);
    float kkn = kk * inv;
    float a = asig[idx];
    float awv = -kkn;
    float bwv = kkn * a;
    float kfv = kv + kavec[c]*(kv*a - kv);
    aw[idx] = awv;
    bw[idx] = bwv;
    kf[idx] = kfv;

    float rv = r[idx];
    drb[idx] = decay[idx] * rv;

    float s1 = bwv*rv, s2 = kfv*rv;
#pragma unroll
    for (int off=16; off; off>>=1){
        s1 += __shfl_xor_sync(0xffffffffu, s1, off);
        s2 += __shfl_xor_sync(0xffffffffu, s2, off);
    }
    __shared__ float red2[8][2];
    if ((tid & 31)==0){ int w = tid>>5; red2[w][0]=s1; red2[w][1]=s2; }
    __syncthreads();
    if (n == 0) {
        float BR = red2[g*2][0] + red2[g*2+1][0];
        float KR = red2[g*2][1] + red2[g*2+1][1];
        int row = (int)(head >> 5);
        int hh  = (int)(head & 31);
        int bb  = row >> 10, t = row & (TT-1);
        size_t off2 = ((size_t)bb*HH + hh)*TT + t;
        brg[off2] = BR;
        krg[off2] = KR;
    }
}

// ---------------------------------------------------------------------------
// K6: WKV7 recurrence — v-split x2 (128 blocks x 128 thr), PF=8 CP16 ring.
//     Halves total LDGSTS traffic vs v-split x4 (each head's data loaded 2x
//     instead of 4x). Thread = (v-row 0..31 = tid>>2, k-quarter = tid&3),
//     S[16]/thread, 2-level shfl over kq.
// ---------------------------------------------------------------------------
#define PF 8

__global__ __launch_bounds__(128) void wkv_kernel(
    const float* __restrict__ dr, const float* __restrict__ k,
    const float* __restrict__ v, const float* __restrict__ d,
    const float* __restrict__ aw, const float* __restrict__ bw,
    const float* __restrict__ brg, const float* __restrict__ krg,
    const float* __restrict__ s0, float* __restrict__ o)
{
    const int blk = blockIdx.x;           // 0..127
    const int bh = blk >> 1;              // 0..63
    const int vh = blk & 1;               // v-half
    const int b = bh >> 5, hh = bh & 31;
    const int tid = threadIdx.x;
    const int vr = tid >> 2;              // 0..31 (local v-row)
    const int kq = tid & 3;
    const int koff = kq * 16;
    const int vg = vh*32 + vr;            // global v-row

    __shared__ float ring[PF][6][64];     // 0=dr 1=k 2=v 3=d 4=aw 5=bw
    __shared__ float brs[TT], krs[TT];

    const size_t rowbase = (size_t)b*TT*CC + hh*64;
    const uint32_t ring0 = smem_u32(ring);

    // CP16 mapping: threads 0..95 copy one float4 per step (6 arrays x 16)
    const float* src16 = nullptr;
    uint32_t doff16 = 0;
    if (tid < 96) {
        int arr = tid >> 4, c4 = tid & 15;
        const float* bp = (arr==0) ? dr : (arr==1) ? k : (arr==2) ? v :
                          (arr==3) ? d : (arr==4) ? aw : bw;
        src16 = bp + rowbase + c4*4;
        doff16 = (uint32_t)((arr*64 + c4*4) * 4);
    }

    // scalar tables
    {
        const float* brp = brg + ((size_t)b*HH + hh)*TT;
        const float* krp = krg + ((size_t)b*HH + hh)*TT;
        for (int i = tid; i < TT; i += 128) { brs[i] = brp[i]; krs[i] = krp[i]; }
    }

    // state: 16 contiguous k-elements per thread
    float S[16];
    {
        const float* sp = s0 + ((size_t)bh*64 + vg)*64 + koff;
#pragma unroll
        for (int i=0;i<16;i++) S[i] = sp[i];
    }

#pragma unroll
    for (int s = 0; s < PF-1; s++) {
        if (tid < 96)
            CP16(ring0 + (uint32_t)s*(6*64*4) + doff16, src16 + (size_t)s*CC);
        CP_COMMIT();
    }

    int buf = 0;
    for (int t = 0; t < TT; t++) {
        asm volatile("cp.async.wait_group %0;" :: "n"(PF-2) : "memory");
        __syncthreads();

        {
            const int ts = t + PF - 1;
            int pbuf = buf - 1; if (pbuf < 0) pbuf += PF;
            if (ts < TT && tid < 96)
                CP16(ring0 + (uint32_t)pbuf*(6*64*4) + doff16, src16 + (size_t)ts*CC);
            CP_COMMIT();
        }

        const float* shdr = ring[buf][0];
        const float* shk  = ring[buf][1];
        const float* shv  = ring[buf][2];
        const float* shd  = ring[buf][3];
        const float* sha  = ring[buf][4];
        const float* shb  = ring[buf][5];

        float4 a4[4], g4[4];
#pragma unroll
        for (int i = 0; i < 4; i++) {
            a4[i] = *(const float4*)&sha[koff + i*4];
            g4[i] = *(const float4*)&shdr[koff + i*4];
        }
        float sa0=0.f, sa1=0.f, sd0=0.f, sd1=0.f;
#pragma unroll
        for (int i = 0; i < 4; i++) {
            sa0 += S[i*4+0]*a4[i].x; sa1 += S[i*4+1]*a4[i].y;
            sa0 += S[i*4+2]*a4[i].z; sa1 += S[i*4+3]*a4[i].w;
            sd0 += S[i*4+0]*g4[i].x; sd1 += S[i*4+1]*g4[i].y;
            sd0 += S[i*4+2]*g4[i].z; sd1 += S[i*4+3]*g4[i].w;
        }
        float sa = sa0 + sa1;
        float sd = sd0 + sd1;
        sa += __shfl_xor_sync(0xffffffffu, sa, 1);
        sd += __shfl_xor_sync(0xffffffffu, sd, 1);
        sa += __shfl_xor_sync(0xffffffffu, sa, 2);
        sd += __shfl_xor_sync(0xffffffffu, sd, 2);

        const float vt = shv[vg];
        if (kq == 0)
            o[rowbase + (size_t)t*CC + vg] = sd + sa*brs[t] + vt*krs[t];

        // S update
#pragma unroll
        for (int i = 0; i < 4; i++) {
            float4 d4 = *(const float4*)&shd[koff + i*4];
            float4 b4 = *(const float4*)&shb[koff + i*4];
            float4 k4 = *(const float4*)&shk[koff + i*4];
            S[i*4+0] = S[i*4+0]*d4.x + sa*b4.x + vt*k4.x;
            S[i*4+1] = S[i*4+1]*d4.y + sa*b4.y + vt*k4.y;
            S[i*4+2] = S[i*4+2]*d4.z + sa*b4.z + vt*k4.z;
            S[i*4+3] = S[i*4+3]*d4.w + sa*b4.w + vt*k4.w;
        }

        buf++; if (buf == PF) buf = 0;
    }
}

// ---------------------------------------------------------------------------
// K7: group norm + per-head bonus + gate multiply -> bf16 hi/lo
// ---------------------------------------------------------------------------
__global__ __launch_bounds__(256) void gn_kernel(
    const float* __restrict__ o, const float* __restrict__ r,
    const float* __restrict__ kf, const float* __restrict__ vf,
    const float* __restrict__ gg, const float* __restrict__ rk,
    const float* __restrict__ gnw, const float* __restrict__ gnb,
    __nv_bfloat16* __restrict__ xoh, __nv_bfloat16* __restrict__ xol)
{
    const int tid = threadIdx.x;
    const int g = tid >> 6, n = tid & 63;
    const size_t head = (size_t)blockIdx.x*4 + g;
    const int h = (int)(head & (HH-1));
    const size_t idx = head*64 + n;
    const int c = h*64 + n;

    float ov = o[idx];
    float rv = r[idx], kv = kf[idx];
    float s1 = ov, s2 = ov*ov, s3 = rv*kv*rk[c];
#pragma unroll
    for (int off=16; off; off>>=1){
        s1 += __shfl_xor_sync(0xffffffffu, s1, off);
        s2 += __shfl_xor_sync(0xffffffffu, s2, off);
        s3 += __shfl_xor_sync(0xffffffffu, s3, off);
    }
    __shared__ float red[8][3];
    if ((tid & 31)==0){ int w = tid>>5; red[w][0]=s1; red[w][1]=s2; red[w][2]=s3; }
    __syncthreads();
    float S1 = red[g*2][0]+red[g*2+1][0];
    float S2 = red[g*2][1]+red[g*2+1][1];
    float S3 = red[g*2][2]+red[g*2+1][2];
    float mu = S1*(1.f/64.f);
    float var = S2*(1.f/64.f) - mu*mu;
    float y = (ov-mu)*rsqrtf(var + 6.4e-4f)*gnw[c] + gnb[c] + S3*vf[idx];
    float xo = y * gg[idx];
    __nv_bfloat16 hv, lv;
    split_hilo(xo, hv, lv);
    xoh[idx] = hv;
    xol[idx] = lv;
}

// ---------------------------------------------------------------------------
// Launch
// ---------------------------------------------------------------------------
extern "C" void kernel_launch(void* const* d_in, const int* in_sizes, int n_in,
                              void* d_out, int out_size)
{
    const float* h      = (const float*)d_in[0];
    const float* shift  = (const float*)d_in[1];
    const float* s0     = (const float*)d_in[2];
    const float* vfirst = (const float*)d_in[3];
    const float* x_r = (const float*)d_in[4];
    const float* x_w = (const float*)d_in[5];
    const float* x_k = (const float*)d_in[6];
    const float* x_v = (const float*)d_in[7];
    const float* x_a = (const float*)d_in[8];
    const float* x_g = (const float*)d_in[9];
    const float* w0 = (const float*)d_in[10];
    const float* w1 = (const float*)d_in[11];
    const float* w2 = (const float*)d_in[12];
    const float* a0 = (const float*)d_in[13];
    const float* a1 = (const float*)d_in[14];
    const float* a2 = (const float*)d_in[15];
    const float* v0 = (const float*)d_in[16];
    const float* v1 = (const float*)d_in[17];
    const float* v2 = (const float*)d_in[18];
    const float* g1 = (const float*)d_in[19];
    const float* g2 = (const float*)d_in[20];
    const float* k_k = (const float*)d_in[21];
    const float* k_a = (const float*)d_in[22];
    const float* r_k = (const float*)d_in[23];
    const float* W_r = (const float*)d_in[24];
    const float* W_k = (const float*)d_in[25];
    const float* W_v = (const float*)d_in[26];
    const float* W_o = (const float*)d_in[27];
    const float* gnw = (const float*)d_in[28];
    const float* gnb = (const float*)d_in[29];
    float* out = (float*)d_out;

    float* S = nullptr;
    cudaGetSymbolAddress((void**)&S, g_scratch);

    float* xw    = S + (size_t)S_XW*BTC;
    float* xa    = S + (size_t)S_XA*BTC;
    float* xv    = S + (size_t)S_XV*BTC;
    float* xg    = S + (size_t)S_XG*BTC;
    float* rb    = S + (size_t)S_R*BTC;
    float* kb    = S + (size_t)S_K*BTC;
    float* vb    = S + (size_t)S_V*BTC;
    float* decay = S + (size_t)S_DECAY*BTC;
    float* asig  = S + (size_t)S_ASIG*BTC;
    float* gbuf  = S + (size_t)S_G*BTC;
    float* awb   = S + (size_t)S_AW*BTC;
    float* bwb   = S + (size_t)S_BW*BTC;
    float* kfb   = S + (size_t)S_KF*BTC;
    float* vfb   = S + (size_t)S_VF*BTC;
    float* ob    = S + (size_t)S_O*BTC;
    float* drb   = S + (size_t)S_DR*BTC;

    __nv_bfloat16* bfb = (__nv_bfloat16*)(S + BF16_BASE);
#define BF(i) (bfb + (size_t)(i)*BTC)
    __nv_bfloat16 *xrh=BF(B_XRH), *xrl=BF(B_XRL), *xkh=BF(B_XKH), *xkl=BF(B_XKL);
    __nv_bfloat16 *xvh=BF(B_XVH), *xvl=BF(B_XVL), *xoh=BF(B_XOH), *xol=BF(B_XOL);
    __nv_bfloat16 *wrh=BF(B_WRH), *wrl=BF(B_WRL), *wkh=BF(B_WKH), *wkl=BF(B_WKL);
    __nv_bfloat16 *wvh=BF(B_WVH), *wvl=BF(B_WVL), *woh=BF(B_WOH), *wol=BF(B_WOL);
#undef BF
    __nv_bfloat16* ub = (__nv_bfloat16*)(S + U_OFF);
    __nv_bfloat16 *uwh = ub,                     *uwl = uwh + (size_t)BT*64;
    __nv_bfloat16 *uah = uwl + (size_t)BT*64,    *ual = uah + (size_t)BT*64;
    __nv_bfloat16 *uvh = ual + (size_t)BT*64,    *uvl = uvh + (size_t)BT*32;
    __nv_bfloat16 *ugh = uvl + (size_t)BT*32,    *ugl = ugh + (size_t)BT*128;
    __nv_bfloat16* vtb = (__nv_bfloat16*)(S + V2T_OFF);
    __nv_bfloat16 *w2h = vtb,                    *w2l = w2h + (size_t)CC*64;
    __nv_bfloat16 *a2h = w2l + (size_t)CC*64,    *a2l = a2h + (size_t)CC*64;
    __nv_bfloat16 *v2h = a2l + (size_t)CC*64,    *v2l = v2h + (size_t)CC*32;
    __nv_bfloat16 *g2h = v2l + (size_t)CC*32,    *g2l = g2h + (size_t)CC*128;

    float* brg = S + BR_OFF;  float* krg = S + KR_OFF;

    cudaFuncSetAttribute(gemm_lora_kernel,
                         cudaFuncAttributeMaxDynamicSharedMemorySize, GEMM_SMEM);
    cudaFuncSetAttribute(stage2_hmma,
                         cudaFuncAttributeMaxDynamicSharedMemorySize, GEMM_SMEM);

    // 0a. big weight conversions
    CvtJobs cj;
    cj.x[0]=W_r; cj.hi[0]=wrh; cj.lo[0]=wrl;
    cj.x[1]=W_k; cj.hi[1]=wkh; cj.lo[1]=wkl;
    cj.x[2]=W_v; cj.hi[2]=wvh; cj.lo[2]=wvl;
    cj.x[3]=W_o; cj.hi[3]=woh; cj.lo[3]=wol;
    cvt_all_kernel<<<dim3(4096, 4), 256>>>(cj);

    // 0b. V2 transpose + hi/lo
    V2tJobs vj;
    vj.src[0]=w2; vj.dh[0]=w2h; vj.dl[0]=w2l; vj.D[0]=64;
    vj.src[1]=a2; vj.dh[1]=a2h; vj.dl[1]=a2l; vj.D[1]=64;
    vj.src[2]=v2; vj.dh[2]=v2h; vj.dl[2]=v2l; vj.D[2]=32;
    vj.src[3]=g2; vj.dh[3]=g2h; vj.dl[3]=g2l; vj.D[3]=128;
    cvt_v2t_kernel<<<dim3(1024, 4), 256>>>(vj);

    // 1. token shift + mixes
    mix_kernel<<<4096, 256>>>(h, shift, x_r, x_w, x_k, x_v, x_a, x_g,
                              xrh, xrl, xw, xkh, xkl, xv, xvh, xvl, xa, xg);

    // 2+3. FUSED: r/k/v projections (z=0..2, 128x128 tiles) + LoRA stage 1 (z=3)
    FusedJobs fj;
    fj.g[0] = { xrh, xrl, wrh, wrl, rb };
    fj.g[1] = { xkh, xkl, wkh, wkl, kb };
    fj.g[2] = { xvh, xvl, wvh, wvl, vb };
    fj.l[0] = { xw, w1, uwh, uwl,  64, 0, 1 };   // tanh
    fj.l[1] = { xa, a1, uah, ual,  64, 0, 0 };
    fj.l[2] = { xv, v1, uvh, uvl,  32, 0, 0 };
    fj.l[3] = { xg, g1, ugh, ugl, 128, 0, 2 };   // sigmoid
    fj.l[4] = { xg, g1, ugh, ugl, 128, 64, 2 };  // sigmoid
    gemm_lora_kernel<<<dim3(16, 16, 4), 256, GEMM_SMEM>>>(fj, 3);

    // 4. LoRA stage 2 on HMMA + fused epilogues
    S2Jobs sj;
    sj.j[0] = { uwh, uwl, w2h, w2l, w0, decay, nullptr, nullptr,  64, 0 };
    sj.j[1] = { uah, ual, a2h, a2l, a0, asig,  nullptr, nullptr,  64, 1 };
    sj.j[2] = { uvh, uvl, v2h, v2l, v0, vfb,   vb,      vfirst,   32, 2 };
    sj.j[3] = { ugh, ugl, g2h, g2l, nullptr, gbuf, nullptr, nullptr, 128, 3 };
    stage2_hmma<<<dim3(16, 16, 4), 256, GEMM_SMEM>>>(sj);

    // 5. prep + per-step scalars + dr
    prep_kernel<<<BT*HH/4, 256>>>(kb, rb, asig, decay, k_k, k_a,
                                  awb, bwb, kfb, drb, brg, krg);

    // 6. WKV7 recurrence (v-split x2: 128 blocks, half the LDGSTS traffic)
    wkv_kernel<<<BB*HH*2, 128>>>(drb, kfb, vfb, decay, awb, bwb, brg, krg, s0, ob);

    // 7. group norm + bonus + gate
    gn_kernel<<<BT*HH/4, 256>>>(ob, rb, kfb, vfb, gbuf, r_k, gnw, gnb, xoh, xol);

    // 8. output projection (256 CTAs = 1 clean wave at 2 CTAs/SM)
    FusedJobs oj = fj;
    oj.g[0] = { xoh, xol, woh, wol, out };
    gemm_lora_kernel<<<dim3(16, 16, 1), 256, GEMM_SMEM>>>(oj, 1);
}

// round 17
// speedup vs baseline: 1.0530x; 1.0530x over previous
#include <cuda_runtime.h>
#include <cuda_bf16.h>
#include <math.h>
#include <cstdint>

// Problem constants
#define BB 2
#define TT 1024
#define CC 2048
#define HH 32
#define NN 64
#define BT (BB*TT)              // 2048
#define BTC (BB*TT*CC)          // 4194304  (== CC*CC)

// ---------------------------------------------------------------------------
// Scratch (static device memory)
// ---------------------------------------------------------------------------
enum { S_XW=0, S_XA, S_XV, S_XG, S_R, S_K, S_V,
       S_DECAY, S_ASIG, S_G, S_AW, S_BW, S_KF, S_VF, S_O, S_DR, N_F32 };
enum { B_XRH=0, B_XRL, B_XKH, B_XKL, B_XVH, B_XVL, B_XOH, B_XOL,
       B_WRH, B_WRL, B_WKH, B_WKL, B_WVH, B_WVL, B_WOH, B_WOL, N_BF16 };
#define BF16_BASE ((size_t)N_F32*BTC)                 // in floats
#define U_OFF     (BF16_BASE + (size_t)N_BF16*BTC/2)  // bf16 U region
#define BR_OFF    (U_OFF + (size_t)BT*288)
#define KR_OFF    (BR_OFF + (size_t)BB*HH*TT)
#define V2T_OFF   (KR_OFF + (size_t)BB*HH*TT)         // bf16 V2T region
#define SCRATCH_FLOATS (V2T_OFF + (size_t)CC*288 + 256)

__device__ float g_scratch[SCRATCH_FLOATS];

// ---------------------------------------------------------------------------
// PTX helpers
// ---------------------------------------------------------------------------
__device__ __forceinline__ uint32_t smem_u32(const void* p) {
    uint32_t a;
    asm("{ .reg .u64 t; cvta.to.shared.u64 t, %1; cvt.u32.u64 %0, t; }" : "=r"(a) : "l"(p));
    return a;
}
#define CP16(dst, src) \
    asm volatile("cp.async.cg.shared.global [%0], [%1], 16;" :: "r"(dst), "l"(src))
#define CP_COMMIT() asm volatile("cp.async.commit_group;" ::: "memory")
#define LDSM4(r, addr) \
    asm volatile("ldmatrix.sync.aligned.m8n8.x4.shared.b16 {%0,%1,%2,%3}, [%4];" \
        : "=r"((r)[0]), "=r"((r)[1]), "=r"((r)[2]), "=r"((r)[3]) : "r"(addr))
#define MMA16816(d, a, b0, b1) \
    asm volatile("mma.sync.aligned.m16n8k16.row.col.f32.bf16.bf16.f32 " \
        "{%0,%1,%2,%3}, {%4,%5,%6,%7}, {%8,%9}, {%0,%1,%2,%3};" \
        : "+f"((d)[0]), "+f"((d)[1]), "+f"((d)[2]), "+f"((d)[3]) \
        : "r"((a)[0]), "r"((a)[1]), "r"((a)[2]), "r"((a)[3]), "r"(b0), "r"(b1))

__device__ __forceinline__ void split_hilo(float v, __nv_bfloat16& h, __nv_bfloat16& l) {
    h = __float2bfloat16(v);
    l = __float2bfloat16(v - __bfloat162float(h));
}
__device__ __forceinline__ void store_hilo4(__nv_bfloat16* hi, __nv_bfloat16* lo,
                                            size_t off, float4 v) {
    __nv_bfloat16 hv[4], lv[4];
    split_hilo(v.x, hv[0], lv[0]); split_hilo(v.y, hv[1], lv[1]);
    split_hilo(v.z, hv[2], lv[2]); split_hilo(v.w, hv[3], lv[3]);
    *(uint2*)&hi[off] = *(uint2*)hv;
    *(uint2*)&lo[off] = *(uint2*)lv;
}

// ---------------------------------------------------------------------------
// K0: merged conversions — z<4: big weight hi/lo; z>=4: V2 transpose hi/lo
// ---------------------------------------------------------------------------
struct CvtAllJobs {
    const float* x[4];  __nv_bfloat16* hi[4];  __nv_bfloat16* lo[4];     // big
    const float* src[4]; __nv_bfloat16* dh[4]; __nv_bfloat16* dl[4]; int D[4]; // v2t
};

__global__ __launch_bounds__(256) void cvt_merged_kernel(CvtAllJobs jobs)
{
    const int z = blockIdx.y;
    if (z < 4) {
        size_t i = ((size_t)blockIdx.x * 256 + threadIdx.x) * 4;
        float4 v = *(const float4*)&jobs.x[z][i];
        store_hilo4(jobs.hi[z], jobs.lo[z], i, v);
    } else {
        const int j = z - 4;
        const int D = jobs.D[j];
        int i = blockIdx.x * 256 + threadIdx.x;
        if (i >= CC * D) return;
        int c = i / D, d = i - c * D;
        float v = jobs.src[j][(size_t)d * CC + c];
        __nv_bfloat16 h, l;
        split_hilo(v, h, l);
        jobs.dh[j][i] = h;
        jobs.dl[j][i] = l;
    }
}

// ---------------------------------------------------------------------------
// K1: token shift + 6-way mix
// ---------------------------------------------------------------------------
__global__ __launch_bounds__(256) void mix_kernel(
    const float* __restrict__ h, const float* __restrict__ shift,
    const float* __restrict__ mr, const float* __restrict__ mw,
    const float* __restrict__ mk, const float* __restrict__ mv,
    const float* __restrict__ ma, const float* __restrict__ mg,
    __nv_bfloat16* __restrict__ xrh, __nv_bfloat16* __restrict__ xrl,
    float* __restrict__ oxw,
    __nv_bfloat16* __restrict__ xkh, __nv_bfloat16* __restrict__ xkl,
    float* __restrict__ oxv,
    __nv_bfloat16* __restrict__ xvh, __nv_bfloat16* __restrict__ xvl,
    float* __restrict__ oxa, float* __restrict__ oxg)
{
    int gid = blockIdx.x * 256 + threadIdx.x;
    int row = gid >> 9;
    int c   = (gid & 511) << 2;
    int t   = row & (TT-1);
    int b   = row >> 10;
    size_t off = (size_t)row * CC + c;

    float4 hv = *(const float4*)&h[off];
    float4 pv;
    if (t == 0) pv = *(const float4*)&shift[(size_t)b*CC + c];
    else        pv = *(const float4*)&h[off - CC];
    float4 xx = make_float4(pv.x-hv.x, pv.y-hv.y, pv.z-hv.z, pv.w-hv.w);

#define MIXV(mvec, o)                                                 \
    {   float4 m = *(const float4*)&mvec[c];                          \
        o = make_float4(hv.x + xx.x*m.x, hv.y + xx.y*m.y,             \
                        hv.z + xx.z*m.z, hv.w + xx.w*m.w); }
    float4 vr; MIXV(mr, vr); store_hilo4(xrh, xrl, off, vr);
    float4 vw; MIXV(mw, vw); *(float4*)&oxw[off] = vw;
    float4 vk; MIXV(mk, vk); store_hilo4(xkh, xkl, off, vk);
    float4 vv; MIXV(mv, vv); *(float4*)&oxv[off] = vv; store_hilo4(xvh, xvl, off, vv);
    float4 va; MIXV(ma, va); *(float4*)&oxa[off] = va;
    float4 vg; MIXV(mg, vg); *(float4*)&oxg[off] = vg;
#undef MIXV
}

// ---------------------------------------------------------------------------
// K2: FUSED HMMA bf16x3 GEMM + LoRA stage 1.
//     CTA tile 128x128, warp tile 64x32, 3-stage x 32KB ring -> 2 CTAs/SM.
// ---------------------------------------------------------------------------
#define GSTAGES 3
#define TILE_A 8192              // 128 rows x 64 B
#define TILE_B 8192              // 128 rows x 64 B
#define STAGE_B (2*TILE_A + 2*TILE_B)    // 32768
#define GEMM_SMEM (GSTAGES*STAGE_B)      // 98304

struct GemmJob  { const __nv_bfloat16 *Ah, *Al, *Bh, *Bl; float* Y; };
struct Lora1Job { const float* X; const float* G;
                  __nv_bfloat16* Uh; __nv_bfloat16* Ul; int D; int col0; int act; };
struct FusedJobs { GemmJob g[3]; Lora1Job l[5]; };

__device__ __forceinline__ uint32_t swz(uint32_t row, uint32_t chunk) {
    return row*64u + ((chunk ^ ((row >> 1) & 3u)) << 4);
}

__device__ void gemm_path(const GemmJob& gj, char* dynsmem)
{
    const __nv_bfloat16* __restrict__ Ahi = gj.Ah;
    const __nv_bfloat16* __restrict__ Alo = gj.Al;
    const __nv_bfloat16* __restrict__ Bhi = gj.Bh;
    const __nv_bfloat16* __restrict__ Blo = gj.Bl;
    float* __restrict__ Y = gj.Y;

    const uint32_t sb = smem_u32(dynsmem);
    const int tid  = threadIdx.x;
    const int lane = tid & 31;
    const int warp = tid >> 5;
    const int wm = warp >> 2;            // 0..1 (64 rows each)
    const int wn = warp & 3;             // 0..3 (32 cols each)
    const int bm = blockIdx.y << 7;
    const int bn = blockIdx.x << 7;

    auto load_stage = [&](int chunk, int stage) {
        const uint32_t st = sb + (uint32_t)stage * STAGE_B;
        const int k0 = chunk << 5;
#pragma unroll
        for (int i = 0; i < 2; i++) {                  // A: 512 float4
            int idx = tid + (i << 8);
            int row = idx >> 2, ch = idx & 3;
            uint32_t d = st + swz(row, ch);
            size_t g = (size_t)(bm + row) * CC + k0 + ch * 8;
            CP16(d,          Ahi + g);
            CP16(d + TILE_A, Alo + g);
        }
#pragma unroll
        for (int i = 0; i < 2; i++) {                  // B: 512 float4
            int idx = tid + (i << 8);
            int row = idx >> 2, ch = idx & 3;
            uint32_t d = st + 2*TILE_A + swz(row, ch);
            size_t g = (size_t)(bn + row) * CC + k0 + ch * 8;
            CP16(d,          Bhi + g);
            CP16(d + TILE_B, Blo + g);
        }
    };

    float acc[4][4][4];
#pragma unroll
    for (int mi=0;mi<4;mi++)
#pragma unroll
        for (int ni=0;ni<4;ni++)
#pragma unroll
            for (int j=0;j<4;j++) acc[mi][ni][j] = 0.f;

#pragma unroll
    for (int s = 0; s < 2; s++) { load_stage(s, s); CP_COMMIT(); }

    const int a_row = wm*64 + (lane & 7) + ((lane >> 3) & 1) * 8;
    const int a_ch  = (lane >> 4);
    const int b_row = wn*32 + (lane & 7) + (lane >> 4) * 8;
    const int b_ch  = ((lane >> 3) & 1);

    for (int it = 0; it < 64; it++) {
        const uint32_t st = sb + (uint32_t)(it % 3) * STAGE_B;
        asm volatile("cp.async.wait_group 1;" ::: "memory");
        __syncthreads();
        if (it + 2 < 64) load_stage(it + 2, (it + 2) % 3);
        CP_COMMIT();

#pragma unroll
        for (int ks = 0; ks < 2; ks++) {
            uint32_t ah[4][4], al[4][4], bh[2][4], bl[2][4];
#pragma unroll
            for (int mi = 0; mi < 4; mi++) {
                uint32_t a = st + swz((uint32_t)(a_row + mi*16), (uint32_t)(a_ch + ks*2));
                LDSM4(ah[mi], a);
            }
#pragma unroll
            for (int j = 0; j < 2; j++) {
                uint32_t baddr = st + 2*TILE_A +
                    swz((uint32_t)(b_row + j*16), (uint32_t)(b_ch + ks*2));
                LDSM4(bh[j], baddr);
            }
            // pass 1: ah * bh
#pragma unroll
            for (int mi = 0; mi < 4; mi++)
#pragma unroll
                for (int ni = 0; ni < 4; ni++)
                    MMA16816(acc[mi][ni], ah[mi], bh[ni>>1][(ni&1)*2], bh[ni>>1][(ni&1)*2+1]);
            // pass 2: ah * bl
#pragma unroll
            for (int j = 0; j < 2; j++) {
                uint32_t baddr = st + 2*TILE_A + TILE_B +
                    swz((uint32_t)(b_row + j*16), (uint32_t)(b_ch + ks*2));
                LDSM4(bl[j], baddr);
            }
#pragma unroll
            for (int mi = 0; mi < 4; mi++)
#pragma unroll
                for (int ni = 0; ni < 4; ni++)
                    MMA16816(acc[mi][ni], ah[mi], bl[ni>>1][(ni&1)*2], bl[ni>>1][(ni&1)*2+1]);
            // pass 3: al * bh
#pragma unroll
            for (int mi = 0; mi < 4; mi++) {
                uint32_t a = st + swz((uint32_t)(a_row + mi*16), (uint32_t)(a_ch + ks*2));
                LDSM4(al[mi], a + TILE_A);
            }
#pragma unroll
            for (int mi = 0; mi < 4; mi++)
#pragma unroll
                for (int ni = 0; ni < 4; ni++)
                    MMA16816(acc[mi][ni], al[mi], bh[ni>>1][(ni&1)*2], bh[ni>>1][(ni&1)*2+1]);
        }
    }

    const int erow = bm + wm*64 + (lane >> 2);
    const int ecol = bn + wn*32 + (lane & 3) * 2;
#pragma unroll
    for (int mi = 0; mi < 4; mi++)
#pragma unroll
        for (int ni = 0; ni < 4; ni++) {
            size_t r0 = (size_t)(erow + mi*16) * CC + ecol + ni*8;
            *(float2*)&Y[r0]        = make_float2(acc[mi][ni][0], acc[mi][ni][1]);
            *(float2*)&Y[r0 + 8*CC] = make_float2(acc[mi][ni][2], acc[mi][ni][3]);
        }
}

__device__ void lora_path(const Lora1Job& jb, int mblk, char* dynsmem)
{
    const float* __restrict__ X = jb.X;
    const float* __restrict__ G = jb.G;
    const int D = jb.D, col0 = jb.col0, act = jb.act;

    float* Xs = (float*)dynsmem;            // [32][68]
    float* Gs = Xs + 32*68;                 // [32][64]

    const int tid = threadIdx.x;
    const int bm = mblk * 64;
    const int tx = tid & 15;
    const int ty = tid >> 4;

    float4 px[2], pg[2];
    const int xrow = tid & 63;
    const int xkc0 = (tid >> 6) << 2;
    const int gkr0 = tid >> 4;
    const int gcc  = (tid & 15) << 2;

    auto gload = [&](int k0) {
#pragma unroll
        for (int i = 0; i < 2; i++) {
            px[i] = *(const float4*)&X[(size_t)(bm + xrow)*CC + k0 + xkc0 + i*16];
            if (col0 + gcc < D)
                pg[i] = *(const float4*)&G[(size_t)(k0 + gkr0 + i*16)*D + col0 + gcc];
            else
                pg[i] = make_float4(0.f, 0.f, 0.f, 0.f);
        }
    };
    auto sstore = [&]() {
#pragma unroll
        for (int i = 0; i < 2; i++) {
            int kc = xkc0 + i*16;
            Xs[(kc+0)*68+xrow] = px[i].x; Xs[(kc+1)*68+xrow] = px[i].y;
            Xs[(kc+2)*68+xrow] = px[i].z; Xs[(kc+3)*68+xrow] = px[i].w;
            *(float4*)&Gs[(gkr0 + i*16)*64 + gcc] = pg[i];
        }
    };

    float acc[4][4];
#pragma unroll
    for (int i=0;i<4;i++)
#pragma unroll
        for (int j=0;j<4;j++) acc[i][j] = 0.f;

    gload(0); sstore(); __syncthreads();

    for (int k0 = 32; k0 <= 2048; k0 += 32) {
        if (k0 < 2048) gload(k0);
#pragma unroll
        for (int kk = 0; kk < 32; kk++) {
            float4 xa = *(const float4*)&Xs[kk*68 + ty*4];
            float4 gb = *(const float4*)&Gs[kk*64 + tx*4];
            float xv[4] = {xa.x, xa.y, xa.z, xa.w};
            float gv[4] = {gb.x, gb.y, gb.z, gb.w};
#pragma unroll
            for (int i=0;i<4;i++)
#pragma unroll
                for (int j=0;j<4;j++)
                    acc[i][j] += xv[i]*gv[j];
        }
        __syncthreads();
        if (k0 < 2048) { sstore(); __syncthreads(); }
    }

#pragma unroll
    for (int i=0;i<4;i++) {
        int row = bm + ty*4 + i;
#pragma unroll
        for (int j=0;j<4;j++) {
            int col = col0 + tx*4 + j;
            if (col < D) {
                float y = acc[i][j];
                if (act == 1) y = tanhf(y);
                else if (act == 2) y = 1.f/(1.f+expf(-y));
                __nv_bfloat16 hv, lv;
                split_hilo(y, hv, lv);
                jb.Uh[(size_t)row*D + col] = hv;
                jb.Ul[(size_t)row*D + col] = lv;
            }
        }
    }
}

__global__ __launch_bounds__(256, 2) void gemm_lora_kernel(FusedJobs jobs, int nz_gemm)
{
    extern __shared__ char dynsmem[];
    const int z = blockIdx.z;
    if (z < nz_gemm) {
        gemm_path(jobs.g[z], dynsmem);
    } else {
        int lin = (z - nz_gemm)*256 + blockIdx.y*16 + blockIdx.x;
        if (lin >= 160) return;
        lora_path(jobs.l[lin >> 5], lin & 31, dynsmem);
    }
}

// ---------------------------------------------------------------------------
// K4: stage2 on HMMA (128x128 tile, 2 CTAs/SM)
// ---------------------------------------------------------------------------
struct S2Job  { const __nv_bfloat16 *Ah, *Al, *Bh, *Bl; const float* bias;
                float* out; const float* e1; const float* e2; int D; int mode; };
struct S2Jobs { S2Job j[4]; };

__global__ __launch_bounds__(256, 2) void stage2_hmma(S2Jobs jobs)
{
    extern __shared__ char dynsmem[];
    const S2Job jb = jobs.j[blockIdx.z];
    const int D = jb.D, nk = D >> 5, mode = jb.mode;

    const uint32_t sb = smem_u32(dynsmem);
    const int tid  = threadIdx.x;
    const int lane = tid & 31;
    const int warp = tid >> 5;
    const int wm = warp >> 2;
    const int wn = warp & 3;
    const int bm = blockIdx.y << 7;
    const int bn = blockIdx.x << 7;

    auto load_stage = [&](int chunk, int stage) {
        const uint32_t st = sb + (uint32_t)stage * STAGE_B;
        const int k0 = chunk << 5;
#pragma unroll
        for (int i = 0; i < 2; i++) {
            int idx = tid + (i << 8);
            int row = idx >> 2, ch = idx & 3;
            uint32_t d = st + swz(row, ch);
            size_t g = (size_t)(bm + row) * D + k0 + ch * 8;
            CP16(d,          jb.Ah + g);
            CP16(d + TILE_A, jb.Al + g);
        }
#pragma unroll
        for (int i = 0; i < 2; i++) {
            int idx = tid + (i << 8);
            int row = idx >> 2, ch = idx & 3;
            uint32_t d = st + 2*TILE_A + swz(row, ch);
            size_t g = (size_t)(bn + row) * D + k0 + ch * 8;
            CP16(d,          jb.Bh + g);
            CP16(d + TILE_B, jb.Bl + g);
        }
    };

    float acc[4][4][4];
#pragma unroll
    for (int mi=0;mi<4;mi++)
#pragma unroll
        for (int ni=0;ni<4;ni++)
#pragma unroll
            for (int j=0;j<4;j++) acc[mi][ni][j] = 0.f;

#pragma unroll
    for (int s = 0; s < 2; s++) {
        if (s < nk) load_stage(s, s);
        CP_COMMIT();
    }

    const int a_row = wm*64 + (lane & 7) + ((lane >> 3) & 1) * 8;
    const int a_ch  = (lane >> 4);
    const int b_row = wn*32 + (lane & 7) + (lane >> 4) * 8;
    const int b_ch  = ((lane >> 3) & 1);

    for (int it = 0; it < nk; it++) {
        const uint32_t st = sb + (uint32_t)(it % 3) * STAGE_B;
        asm volatile("cp.async.wait_group 1;" ::: "memory");
        __syncthreads();
        if (it + 2 < nk) load_stage(it + 2, (it + 2) % 3);
        CP_COMMIT();

#pragma unroll
        for (int ks = 0; ks < 2; ks++) {
            uint32_t ah[4][4], al[4][4], bh[2][4], bl[2][4];
#pragma unroll
            for (int mi = 0; mi < 4; mi++) {
                uint32_t a = st + swz((uint32_t)(a_row + mi*16), (uint32_t)(a_ch + ks*2));
                LDSM4(ah[mi], a);
            }
#pragma unroll
            for (int j = 0; j < 2; j++) {
                uint32_t baddr = st + 2*TILE_A +
                    swz((uint32_t)(b_row + j*16), (uint32_t)(b_ch + ks*2));
                LDSM4(bh[j], baddr);
            }
#pragma unroll
            for (int mi = 0; mi < 4; mi++)
#pragma unroll
                for (int ni = 0; ni < 4; ni++)
                    MMA16816(acc[mi][ni], ah[mi], bh[ni>>1][(ni&1)*2], bh[ni>>1][(ni&1)*2+1]);
#pragma unroll
            for (int j = 0; j < 2; j++) {
                uint32_t baddr = st + 2*TILE_A + TILE_B +
                    swz((uint32_t)(b_row + j*16), (uint32_t)(b_ch + ks*2));
                LDSM4(bl[j], baddr);
            }
#pragma unroll
            for (int mi = 0; mi < 4; mi++)
#pragma unroll
                for (int ni = 0; ni < 4; ni++)
                    MMA16816(acc[mi][ni], ah[mi], bl[ni>>1][(ni&1)*2], bl[ni>>1][(ni&1)*2+1]);
#pragma unroll
            for (int mi = 0; mi < 4; mi++) {
                uint32_t a = st + swz((uint32_t)(a_row + mi*16), (uint32_t)(a_ch + ks*2));
                LDSM4(al[mi], a + TILE_A);
            }
#pragma unroll
            for (int mi = 0; mi < 4; mi++)
#pragma unroll
                for (int ni = 0; ni < 4; ni++)
                    MMA16816(acc[mi][ni], al[mi], bh[ni>>1][(ni&1)*2], bh[ni>>1][(ni&1)*2+1]);
        }
    }

    const int erow = bm + wm*64 + (lane >> 2);
    const int ecol = bn + wn*32 + (lane & 3) * 2;
#pragma unroll
    for (int mi = 0; mi < 4; mi++)
#pragma unroll
        for (int ni = 0; ni < 4; ni++) {
            const int c = ecol + ni*8;
            size_t r0 = (size_t)(erow + mi*16) * CC + c;
            float2 p0 = make_float2(acc[mi][ni][0], acc[mi][ni][1]);
            float2 p1 = make_float2(acc[mi][ni][2], acc[mi][ni][3]);
            if (mode == 3) {
                *(float2*)&jb.out[r0]        = p0;
                *(float2*)&jb.out[r0 + 8*CC] = p1;
            } else {
                float b0 = jb.bias[c], b1 = jb.bias[c+1];
                float s00 = 1.f/(1.f+expf(-(p0.x+b0)));
                float s01 = 1.f/(1.f+expf(-(p0.y+b1)));
                float s10 = 1.f/(1.f+expf(-(p1.x+b0)));
                float s11 = 1.f/(1.f+expf(-(p1.y+b1)));
                if (mode == 0) {
                    const float e = 0.6065306597126334f;
                    *(float2*)&jb.out[r0]        = make_float2(e*s00, e*s01);
                    *(float2*)&jb.out[r0 + 8*CC] = make_float2(e*s10, e*s11);
                } else if (mode == 1) {
                    *(float2*)&jb.out[r0]        = make_float2(s00, s01);
                    *(float2*)&jb.out[r0 + 8*CC] = make_float2(s10, s11);
                } else {
                    float2 a0 = *(const float2*)&jb.e1[r0];
                    float2 f0 = *(const float2*)&jb.e2[r0];
                    float2 a1 = *(const float2*)&jb.e1[r0 + 8*CC];
                    float2 f1 = *(const float2*)&jb.e2[r0 + 8*CC];
                    *(float2*)&jb.out[r0] =
                        make_float2(a0.x + (f0.x-a0.x)*s00, a0.y + (f0.y-a0.y)*s01);
                    *(float2*)&jb.out[r0 + 8*CC] =
                        make_float2(a1.x + (f1.x-a1.x)*s10, a1.y + (f1.y-a1.y)*s11);
                }
            }
        }
}

// ---------------------------------------------------------------------------
// K5: per-(b,t,h) prep + per-step scalars + dr = decay*r
// ---------------------------------------------------------------------------
__global__ __launch_bounds__(256) void prep_kernel(
    const float* __restrict__ k, const float* __restrict__ r,
    const float* __restrict__ asig, const float* __restrict__ decay,
    const float* __restrict__ kkvec, const float* __restrict__ kavec,
    float* __restrict__ aw, float* __restrict__ bw, float* __restrict__ kf,
    float* __restrict__ drb,
    float* __restrict__ brg, float* __restrict__ krg)
{
    const int tid = threadIdx.x;
    const int g = tid >> 6, n = tid & 63;
    const size_t head = (size_t)blockIdx.x*4 + g;
    const size_t idx = head*64 + n;
    const int c = (int)(idx & (CC-1));

    float kv = k[idx];
    float kk = kv * kkvec[c];
    float ss = kk*kk;
#pragma unroll
    for (int off=16; off; off>>=1) ss += __shfl_xor_sync(0xffffffffu, ss, off);
    __shared__ float red[8];
    if ((tid & 31)==0) red[tid>>5] = ss;
    __syncthreads();
    float tot = red[g*2] + red[g*2+1];
    float inv = 1.f / fmaxf(sqrtf(tot), 1e-12f);
    float kkn = kk * inv;
    float a = asig[idx];
    float awv = -kkn;
    float bwv = kkn * a;
    float kfv = kv + kavec[c]*(kv*a - kv);
    aw[idx] = awv;
    bw[idx] = bwv;
    kf[idx] = kfv;

    float rv = r[idx];
    drb[idx] = decay[idx] * rv;

    float s1 = bwv*rv, s2 = kfv*rv;
#pragma unroll
    for (int off=16; off; off>>=1){
        s1 += __shfl_xor_sync(0xffffffffu, s1, off);
        s2 += __shfl_xor_sync(0xffffffffu, s2, off);
    }
    __shared__ float red2[8][2];
    if ((tid & 31)==0){ int w = tid>>5; red2[w][0]=s1; red2[w][1]=s2; }
    __syncthreads();
    if (n == 0) {
        float BR = red2[g*2][0] + red2[g*2+1][0];
        float KR = red2[g*2][1] + red2[g*2+1][1];
        int row = (int)(head >> 5);
        int hh  = (int)(head & 31);
        int bb  = row >> 10, t = row & (TT-1);
        size_t off2 = ((size_t)bb*HH + hh)*TT + t;
        brg[off2] = BR;
        krg[off2] = KR;
    }
}

// ---------------------------------------------------------------------------
// K6: WKV7 recurrence — r15 best config (v-split x4, 256 blocks x 128 thr,
//     PF=8 CP16 ring). Streaming o-stores (__stwt) to keep L2 for the ring.
// ---------------------------------------------------------------------------
#define PF 8

__global__ __launch_bounds__(128) void wkv_kernel(
    const float* __restrict__ dr, const float* __restrict__ k,
    const float* __restrict__ v, const float* __restrict__ d,
    const float* __restrict__ aw, const float* __restrict__ bw,
    const float* __restrict__ brg, const float* __restrict__ krg,
    const float* __restrict__ s0, float* __restrict__ o)
{
    const int blk = blockIdx.x;
    const int bh = blk >> 2;
    const int vq = blk & 3;
    const int b = bh >> 5, hh = bh & 31;
    const int tid = threadIdx.x;
    const int vr = tid >> 3;
    const int kt = tid & 7;
    const int koff = kt * 8;
    const int vg = vq*16 + vr;

    __shared__ float ring[PF][6][64];
    __shared__ float brs[TT], krs[TT];

    const size_t rowbase = (size_t)b*TT*CC + hh*64;
    const uint32_t ring0 = smem_u32(ring);

    const float* src16 = nullptr;
    uint32_t doff16 = 0;
    if (tid < 96) {
        int arr = tid >> 4, c4 = tid & 15;
        const float* bp = (arr==0) ? dr : (arr==1) ? k : (arr==2) ? v :
                          (arr==3) ? d : (arr==4) ? aw : bw;
        src16 = bp + rowbase + c4*4;
        doff16 = (uint32_t)((arr*64 + c4*4) * 4);
    }

    {
        const float* brp = brg + ((size_t)b*HH + hh)*TT;
        const float* krp = krg + ((size_t)b*HH + hh)*TT;
        for (int i = tid; i < TT; i += 128) { brs[i] = brp[i]; krs[i] = krp[i]; }
    }

    float S[8];
    {
        const float* sp = s0 + ((size_t)bh*64 + vg)*64 + koff;
#pragma unroll
        for (int i=0;i<8;i++) S[i] = sp[i];
    }

#pragma unroll
    for (int s = 0; s < PF-1; s++) {
        if (tid < 96)
            CP16(ring0 + (uint32_t)s*(6*64*4) + doff16, src16 + (size_t)s*CC);
        CP_COMMIT();
    }

    int buf = 0;
    for (int t = 0; t < TT; t++) {
        asm volatile("cp.async.wait_group %0;" :: "n"(PF-2) : "memory");
        __syncthreads();

        {
            const int ts = t + PF - 1;
            int pbuf = buf - 1; if (pbuf < 0) pbuf += PF;
            if (ts < TT && tid < 96)
                CP16(ring0 + (uint32_t)pbuf*(6*64*4) + doff16, src16 + (size_t)ts*CC);
            CP_COMMIT();
        }

        const float* shdr = ring[buf][0];
        const float* shk  = ring[buf][1];
        const float* shv  = ring[buf][2];
        const float* shd  = ring[buf][3];
        const float* sha  = ring[buf][4];
        const float* shb  = ring[buf][5];

        float4 a40 = *(const float4*)&sha[koff];
        float4 a41 = *(const float4*)&sha[koff+4];
        float4 g40 = *(const float4*)&shdr[koff];
        float4 g41 = *(const float4*)&shdr[koff+4];

        float sa0, sa1, sd0, sd1;
        sa0 = S[0]*a40.x;           sa1 = S[1]*a40.y;
        sa0 += S[2]*a40.z;          sa1 += S[3]*a40.w;
        sa0 += S[4]*a41.x;          sa1 += S[5]*a41.y;
        sa0 += S[6]*a41.z;          sa1 += S[7]*a41.w;
        sd0 = S[0]*g40.x;           sd1 = S[1]*g40.y;
        sd0 += S[2]*g40.z;          sd1 += S[3]*g40.w;
        sd0 += S[4]*g41.x;          sd1 += S[5]*g41.y;
        sd0 += S[6]*g41.z;          sd1 += S[7]*g41.w;
        float sa = sa0 + sa1;
        float sd = sd0 + sd1;
        sa += __shfl_xor_sync(0xffffffffu, sa, 1);
        sd += __shfl_xor_sync(0xffffffffu, sd, 1);
        sa += __shfl_xor_sync(0xffffffffu, sa, 2);
        sd += __shfl_xor_sync(0xffffffffu, sd, 2);
        sa += __shfl_xor_sync(0xffffffffu, sa, 4);
        sd += __shfl_xor_sync(0xffffffffu, sd, 4);

        const float vt = shv[vg];
        if (kt == 0)
            __stwt(&o[rowbase + (size_t)t*CC + vg], sd + sa*brs[t] + vt*krs[t]);

        float4 d40 = *(const float4*)&shd[koff];
        float4 d41 = *(const float4*)&shd[koff+4];
        float4 b40 = *(const float4*)&shb[koff];
        float4 b41 = *(const float4*)&shb[koff+4];
        float4 k40 = *(const float4*)&shk[koff];
        float4 k41 = *(const float4*)&shk[koff+4];
        S[0] = S[0]*d40.x + sa*b40.x + vt*k40.x;
        S[1] = S[1]*d40.y + sa*b40.y + vt*k40.y;
        S[2] = S[2]*d40.z + sa*b40.z + vt*k40.z;
        S[3] = S[3]*d40.w + sa*b40.w + vt*k40.w;
        S[4] = S[4]*d41.x + sa*b41.x + vt*k41.x;
        S[5] = S[5]*d41.y + sa*b41.y + vt*k41.y;
        S[6] = S[6]*d41.z + sa*b41.z + vt*k41.z;
        S[7] = S[7]*d41.w + sa*b41.w + vt*k41.w;

        buf++; if (buf == PF) buf = 0;
    }
}

// ---------------------------------------------------------------------------
// K7: group norm + per-head bonus + gate multiply -> bf16 hi/lo
// ---------------------------------------------------------------------------
__global__ __launch_bounds__(256) void gn_kernel(
    const float* __restrict__ o, const float* __restrict__ r,
    const float* __restrict__ kf, const float* __restrict__ vf,
    const float* __restrict__ gg, const float* __restrict__ rk,
    const float* __restrict__ gnw, const float* __restrict__ gnb,
    __nv_bfloat16* __restrict__ xoh, __nv_bfloat16* __restrict__ xol)
{
    const int tid = threadIdx.x;
    const int g = tid >> 6, n = tid & 63;
    const size_t head = (size_t)blockIdx.x*4 + g;
    const int h = (int)(head & (HH-1));
    const size_t idx = head*64 + n;
    const int c = h*64 + n;

    float ov = __ldg(&o[idx]);
    float rv = r[idx], kv = kf[idx];
    float s1 = ov, s2 = ov*ov, s3 = rv*kv*rk[c];
#pragma unroll
    for (int off=16; off; off>>=1){
        s1 += __shfl_xor_sync(0xffffffffu, s1, off);
        s2 += __shfl_xor_sync(0xffffffffu, s2, off);
        s3 += __shfl_xor_sync(0xffffffffu, s3, off);
    }
    __shared__ float red[8][3];
    if ((tid & 31)==0){ int w = tid>>5; red[w][0]=s1; red[w][1]=s2; red[w][2]=s3; }
    __syncthreads();
    float S1 = red[g*2][0]+red[g*2+1][0];
    float S2 = red[g*2][1]+red[g*2+1][1];
    float S3 = red[g*2][2]+red[g*2+1][2];
    float mu = S1*(1.f/64.f);
    float var = S2*(1.f/64.f) - mu*mu;
    float y = (ov-mu)*rsqrtf(var + 6.4e-4f)*gnw[c] + gnb[c] + S3*vf[idx];
    float xo = y * gg[idx];
    __nv_bfloat16 hv, lv;
    split_hilo(xo, hv, lv);
    xoh[idx] = hv;
    xol[idx] = lv;
}

// ---------------------------------------------------------------------------
// Launch
// ---------------------------------------------------------------------------
extern "C" void kernel_launch(void* const* d_in, const int* in_sizes, int n_in,
                              void* d_out, int out_size)
{
    const float* h      = (const float*)d_in[0];
    const float* shift  = (const float*)d_in[1];
    const float* s0     = (const float*)d_in[2];
    const float* vfirst = (const float*)d_in[3];
    const float* x_r = (const float*)d_in[4];
    const float* x_w = (const float*)d_in[5];
    const float* x_k = (const float*)d_in[6];
    const float* x_v = (const float*)d_in[7];
    const float* x_a = (const float*)d_in[8];
    const float* x_g = (const float*)d_in[9];
    const float* w0 = (const float*)d_in[10];
    const float* w1 = (const float*)d_in[11];
    const float* w2 = (const float*)d_in[12];
    const float* a0 = (const float*)d_in[13];
    const float* a1 = (const float*)d_in[14];
    const float* a2 = (const float*)d_in[15];
    const float* v0 = (const float*)d_in[16];
    const float* v1 = (const float*)d_in[17];
    const float* v2 = (const float*)d_in[18];
    const float* g1 = (const float*)d_in[19];
    const float* g2 = (const float*)d_in[20];
    const float* k_k = (const float*)d_in[21];
    const float* k_a = (const float*)d_in[22];
    const float* r_k = (const float*)d_in[23];
    const float* W_r = (const float*)d_in[24];
    const float* W_k = (const float*)d_in[25];
    const float* W_v = (const float*)d_in[26];
    const float* W_o = (const float*)d_in[27];
    const float* gnw = (const float*)d_in[28];
    const float* gnb = (const float*)d_in[29];
    float* out = (float*)d_out;

    float* S = nullptr;
    cudaGetSymbolAddress((void**)&S, g_scratch);

    float* xw    = S + (size_t)S_XW*BTC;
    float* xa    = S + (size_t)S_XA*BTC;
    float* xv    = S + (size_t)S_XV*BTC;
    float* xg    = S + (size_t)S_XG*BTC;
    float* rb    = S + (size_t)S_R*BTC;
    float* kb    = S + (size_t)S_K*BTC;
    float* vb    = S + (size_t)S_V*BTC;
    float* decay = S + (size_t)S_DECAY*BTC;
    float* asig  = S + (size_t)S_ASIG*BTC;
    float* gbuf  = S + (size_t)S_G*BTC;
    float* awb   = S + (size_t)S_AW*BTC;
    float* bwb   = S + (size_t)S_BW*BTC;
    float* kfb   = S + (size_t)S_KF*BTC;
    float* vfb   = S + (size_t)S_VF*BTC;
    float* ob    = S + (size_t)S_O*BTC;
    float* drb   = S + (size_t)S_DR*BTC;

    __nv_bfloat16* bfb = (__nv_bfloat16*)(S + BF16_BASE);
#define BF(i) (bfb + (size_t)(i)*BTC)
    __nv_bfloat16 *xrh=BF(B_XRH), *xrl=BF(B_XRL), *xkh=BF(B_XKH), *xkl=BF(B_XKL);
    __nv_bfloat16 *xvh=BF(B_XVH), *xvl=BF(B_XVL), *xoh=BF(B_XOH), *xol=BF(B_XOL);
    __nv_bfloat16 *wrh=BF(B_WRH), *wrl=BF(B_WRL), *wkh=BF(B_WKH), *wkl=BF(B_WKL);
    __nv_bfloat16 *wvh=BF(B_WVH), *wvl=BF(B_WVL), *woh=BF(B_WOH), *wol=BF(B_WOL);
#undef BF
    __nv_bfloat16* ub = (__nv_bfloat16*)(S + U_OFF);
    __nv_bfloat16 *uwh = ub,                     *uwl = uwh + (size_t)BT*64;
    __nv_bfloat16 *uah = uwl + (size_t)BT*64,    *ual = uah + (size_t)BT*64;
    __nv_bfloat16 *uvh = ual + (size_t)BT*64,    *uvl = uvh + (size_t)BT*32;
    __nv_bfloat16 *ugh = uvl + (size_t)BT*32,    *ugl = ugh + (size_t)BT*128;
    __nv_bfloat16* vtb = (__nv_bfloat16*)(S + V2T_OFF);
    __nv_bfloat16 *w2h = vtb,                    *w2l = w2h + (size_t)CC*64;
    __nv_bfloat16 *a2h = w2l + (size_t)CC*64,    *a2l = a2h + (size_t)CC*64;
    __nv_bfloat16 *v2h = a2l + (size_t)CC*64,    *v2l = v2h + (size_t)CC*32;
    __nv_bfloat16 *g2h = v2l + (size_t)CC*32,    *g2l = g2h + (size_t)CC*128;

    float* brg = S + BR_OFF;  float* krg = S + KR_OFF;

    cudaFuncSetAttribute(gemm_lora_kernel,
                         cudaFuncAttributeMaxDynamicSharedMemorySize, GEMM_SMEM);
    cudaFuncSetAttribute(stage2_hmma,
                         cudaFuncAttributeMaxDynamicSharedMemorySize, GEMM_SMEM);

    // 0. merged conversions (big weights hi/lo + V2 transpose hi/lo)
    CvtAllJobs cj;
    cj.x[0]=W_r; cj.hi[0]=wrh; cj.lo[0]=wrl;
    cj.x[1]=W_k; cj.hi[1]=wkh; cj.lo[1]=wkl;
    cj.x[2]=W_v; cj.hi[2]=wvh; cj.lo[2]=wvl;
    cj.x[3]=W_o; cj.hi[3]=woh; cj.lo[3]=wol;
    cj.src[0]=w2; cj.dh[0]=w2h; cj.dl[0]=w2l; cj.D[0]=64;
    cj.src[1]=a2; cj.dh[1]=a2h; cj.dl[1]=a2l; cj.D[1]=64;
    cj.src[2]=v2; cj.dh[2]=v2h; cj.dl[2]=v2l; cj.D[2]=32;
    cj.src[3]=g2; cj.dh[3]=g2h; cj.dl[3]=g2l; cj.D[3]=128;
    cvt_merged_kernel<<<dim3(4096, 8), 256>>>(cj);

    // 1. token shift + mixes
    mix_kernel<<<4096, 256>>>(h, shift, x_r, x_w, x_k, x_v, x_a, x_g,
                              xrh, xrl, xw, xkh, xkl, xv, xvh, xvl, xa, xg);

    // 2+3. FUSED: r/k/v projections (z=0..2, 128x128 tiles) + LoRA stage 1 (z=3)
    FusedJobs fj;
    fj.g[0] = { xrh, xrl, wrh, wrl, rb };
    fj.g[1] = { xkh, xkl, wkh, wkl, kb };
    fj.g[2] = { xvh, xvl, wvh, wvl, vb };
    fj.l[0] = { xw, w1, uwh, uwl,  64, 0, 1 };   // tanh
    fj.l[1] = { xa, a1, uah, ual,  64, 0, 0 };
    fj.l[2] = { xv, v1, uvh, uvl,  32, 0, 0 };
    fj.l[3] = { xg, g1, ugh, ugl, 128, 0, 2 };   // sigmoid
    fj.l[4] = { xg, g1, ugh, ugl, 128, 64, 2 };  // sigmoid
    gemm_lora_kernel<<<dim3(16, 16, 4), 256, GEMM_SMEM>>>(fj, 3);

    // 4. LoRA stage 2 on HMMA + fused epilogues
    S2Jobs sj;
    sj.j[0] = { uwh, uwl, w2h, w2l, w0, decay, nullptr, nullptr,  64, 0 };
    sj.j[1] = { uah, ual, a2h, a2l, a0, asig,  nullptr, nullptr,  64, 1 };
    sj.j[2] = { uvh, uvl, v2h, v2l, v0, vfb,   vb,      vfirst,   32, 2 };
    sj.j[3] = { ugh, ugl, g2h, g2l, nullptr, gbuf, nullptr, nullptr, 128, 3 };
    stage2_hmma<<<dim3(16, 16, 4), 256, GEMM_SMEM>>>(sj);

    // 5. prep + per-step scalars + dr
    prep_kernel<<<BT*HH/4, 256>>>(kb, rb, asig, decay, k_k, k_a,
                                  awb, bwb, kfb, drb, brg, krg);

    // 6. WKV7 recurrence (r15 best config: v-split x4, PF=8)
    wkv_kernel<<<BB*HH*4, 128>>>(drb, kfb, vfb, decay, awb, bwb, brg, krg, s0, ob);

    // 7. group norm + bonus + gate
    gn_kernel<<<BT*HH/4, 256>>>(ob, rb, kfb, vfb, gbuf, r_k, gnw, gnb, xoh, xol);

    // 8. output projection (256 CTAs = 1 clean wave at 2 CTAs/SM)
    FusedJobs oj = fj;
    oj.g[0] = { xoh, xol, woh, wol, out };
    gemm_lora_kernel<<<dim3(16, 16, 1), 256, GEMM_SMEM>>>(oj, 1);
}